// round 2
// baseline (speedup 1.0000x reference)
#include <cuda_runtime.h>
#include <cstdint>

// Problem constants
#define Bn  1024
#define Sn  128
#define En  256
#define Hn  8
#define Dn  64
#define HDn 512

// Scratch for Q,K,V in per-(b,h) [128 x 64] row-major tiles.
// 1024*8*128*64 = 67,108,864 floats = 256 MiB each.
__device__ float g_Q[67108864];
__device__ float g_K[67108864];
__device__ float g_V[67108864];

// ---------------- f32x2 packed-FMA helpers (ptxas won't emit FFMA2 itself) ----
__device__ __forceinline__ unsigned long long dup2(float a) {
    unsigned int u = __float_as_uint(a);
    unsigned long long r;
    asm("mov.b64 %0, {%1, %1};" : "=l"(r) : "r"(u));
    return r;
}
__device__ __forceinline__ void ffma2(unsigned long long &d,
                                      unsigned long long a,
                                      unsigned long long b) {
    asm("fma.rn.f32x2 %0, %1, %2, %0;" : "+l"(d) : "l"(a), "l"(b));
}
__device__ __forceinline__ void unpack2(unsigned long long v, float &lo, float &hi) {
    unsigned int a, b;
    asm("mov.b64 {%0, %1}, %2;" : "=r"(a), "=r"(b) : "l"(v));
    lo = __uint_as_float(a);
    hi = __uint_as_float(b);
}

// =============================================================================
// Kernel 1: fused QKVR projection GEMM.
// C[128x128] = X_b[128x256] @ W[:, n0:n0+128], one CTA per (n_tile, batch).
// grid = (16, 1024): x -> which weight (x>>2) and 128-col tile (x&3), y -> batch
// =============================================================================
__global__ __launch_bounds__(256, 2)
void proj_kernel(const float* __restrict__ X,
                 const float* __restrict__ Wq, const float* __restrict__ Wk,
                 const float* __restrict__ Wv, const float* __restrict__ Wr,
                 float* __restrict__ out)
{
    __shared__ float As[2][16 * 128];   // A transposed: As[k][m]
    __shared__ float Bs[2][16 * 128];   // Bs[k][n]

    const int tid = threadIdx.x;
    const int bx  = blockIdx.x;
    const int b   = blockIdx.y;
    const int tx  = tid & 15;       // 8 output cols
    const int ty  = tid >> 4;       // 8 output rows

    const int w  = bx >> 2;
    const float* W = (w == 0) ? Wq : (w == 1) ? Wk : (w == 2) ? Wv : Wr;
    const int n0 = (bx & 3) * 128;

    const float4* A4 = (const float4*)(X + (size_t)b * Sn * En);
    const float4* W4 = (const float4*)W;

    // Per-thread load coordinates (2 float4 per tile for A and for B)
    const int fa0 = tid, fa1 = tid + 256;
    const int ra0 = fa0 >> 2, ka0 = (fa0 & 3) * 4;
    const int ra1 = fa1 >> 2, ka1 = (fa1 & 3) * 4;
    const int kb0 = fa0 >> 5, nb0 = fa0 & 31;
    const int kb1 = fa1 >> 5, nb1 = fa1 & 31;

    float4 pa0, pa1, pb0, pb1;

    auto ldg = [&](int k0) {
        pa0 = A4[ra0 * 64 + ((k0 + ka0) >> 2)];
        pa1 = A4[ra1 * 64 + ((k0 + ka1) >> 2)];
        pb0 = W4[(k0 + kb0) * 128 + (n0 >> 2) + nb0];
        pb1 = W4[(k0 + kb1) * 128 + (n0 >> 2) + nb1];
    };
    auto sts = [&](int buf) {
        As[buf][(ka0 + 0) * 128 + ra0] = pa0.x;
        As[buf][(ka0 + 1) * 128 + ra0] = pa0.y;
        As[buf][(ka0 + 2) * 128 + ra0] = pa0.z;
        As[buf][(ka0 + 3) * 128 + ra0] = pa0.w;
        As[buf][(ka1 + 0) * 128 + ra1] = pa1.x;
        As[buf][(ka1 + 1) * 128 + ra1] = pa1.y;
        As[buf][(ka1 + 2) * 128 + ra1] = pa1.z;
        As[buf][(ka1 + 3) * 128 + ra1] = pa1.w;
        *(float4*)&Bs[buf][kb0 * 128 + nb0 * 4] = pb0;
        *(float4*)&Bs[buf][kb1 * 128 + nb1 * 4] = pb1;
    };

    ldg(0);
    sts(0);
    __syncthreads();

    unsigned long long acc[8][4];
#pragma unroll
    for (int i = 0; i < 8; ++i)
#pragma unroll
        for (int j = 0; j < 4; ++j) acc[i][j] = 0ull;

#pragma unroll 1
    for (int it = 0; it < 16; ++it) {
        const int buf = it & 1;
        if (it < 15) ldg((it + 1) * 16);
#pragma unroll
        for (int k = 0; k < 16; ++k) {
            const float* ap = &As[buf][k * 128 + ty * 8];
            float4 a0 = *(const float4*)ap;
            float4 a1 = *(const float4*)(ap + 4);
            unsigned long long av[8];
            av[0] = dup2(a0.x); av[1] = dup2(a0.y);
            av[2] = dup2(a0.z); av[3] = dup2(a0.w);
            av[4] = dup2(a1.x); av[5] = dup2(a1.y);
            av[6] = dup2(a1.z); av[7] = dup2(a1.w);
            const unsigned long long* bp =
                (const unsigned long long*)&Bs[buf][k * 128 + tx * 8];
            unsigned long long bv0 = bp[0], bv1 = bp[1], bv2 = bp[2], bv3 = bp[3];
#pragma unroll
            for (int i = 0; i < 8; ++i) {
                ffma2(acc[i][0], av[i], bv0);
                ffma2(acc[i][1], av[i], bv1);
                ffma2(acc[i][2], av[i], bv2);
                ffma2(acc[i][3], av[i], bv3);
            }
        }
        if (it < 15) {
            sts(buf ^ 1);
            __syncthreads();
        }
    }

    // Epilogue
    const int row0 = ty * 8;
    const int nwb  = n0 + tx * 8;   // column within this weight, 0..511
    float c[8];
    if (w < 3) {
        float* G = (w == 0) ? g_Q : (w == 1) ? g_K : g_V;
        const int h  = nwb >> 6;
        const int d0 = nwb & 63;
        float* dst = G + ((size_t)(b * Hn + h) * Sn) * Dn + d0;
#pragma unroll
        for (int i = 0; i < 8; ++i) {
            unpack2(acc[i][0], c[0], c[1]);
            unpack2(acc[i][1], c[2], c[3]);
            unpack2(acc[i][2], c[4], c[5]);
            unpack2(acc[i][3], c[6], c[7]);
            float* p = dst + (size_t)(row0 + i) * Dn;
            *(float4*)p       = make_float4(c[0], c[1], c[2], c[3]);
            *(float4*)(p + 4) = make_float4(c[4], c[5], c[6], c[7]);
        }
    } else {
        float* dst = out + ((size_t)b * Sn) * HDn + nwb;
#pragma unroll
        for (int i = 0; i < 8; ++i) {
            unpack2(acc[i][0], c[0], c[1]);
            unpack2(acc[i][1], c[2], c[3]);
            unpack2(acc[i][2], c[4], c[5]);
            unpack2(acc[i][3], c[6], c[7]);
            float* p = dst + (size_t)(row0 + i) * HDn;
            *(float4*)p       = make_float4(c[0], c[1], c[2], c[3]);
            *(float4*)(p + 4) = make_float4(c[4], c[5], c[6], c[7]);
        }
    }
}

// =============================================================================
// Kernel 2: per-(batch, head) attention: softmax(Q Kᵀ) V + residual, ReLU.
// grid = (8, 1024) = (h, b); 256 threads; 98 KB dynamic smem, 2 CTAs/SM.
// =============================================================================
constexpr int PQ = 132;   // pitch for d-major Qt/Kt (conflict mitigation)

__global__ __launch_bounds__(256)
void attn_kernel(float* __restrict__ out)
{
    extern __shared__ float sm[];
    float* Qt = sm;                 // [64][PQ]   (d-major)
    float* Kt = sm + 64 * PQ;       // [64][PQ]
    float* Vs = sm + 2 * 64 * PQ;   // [128][64]
    float* Ps = sm;                 // [128][PQ]  overlays Qt+Kt (exactly)

    const int tid = threadIdx.x;
    const int h = blockIdx.x, b = blockIdx.y;
    const size_t base = ((size_t)(b * Hn + h) * Sn) * Dn;
    const float4* Qg = (const float4*)(g_Q + base);
    const float4* Kg = (const float4*)(g_K + base);
    const float4* Vg = (const float4*)(g_V + base);

    // Load Q,K transposed (d-major) and V direct.
#pragma unroll
    for (int j = 0; j < 8; ++j) {
        const int f4 = tid + j * 256;          // 0..2047 float4s = 128x64 floats
        const int s  = f4 >> 4;
        const int dq = (f4 & 15) * 4;
        float4 q = Qg[f4], kk = Kg[f4], v = Vg[f4];
        Qt[(dq + 0) * PQ + s] = q.x;  Qt[(dq + 1) * PQ + s] = q.y;
        Qt[(dq + 2) * PQ + s] = q.z;  Qt[(dq + 3) * PQ + s] = q.w;
        Kt[(dq + 0) * PQ + s] = kk.x; Kt[(dq + 1) * PQ + s] = kk.y;
        Kt[(dq + 2) * PQ + s] = kk.z; Kt[(dq + 3) * PQ + s] = kk.w;
        *(float4*)&Vs[f4 * 4] = v;
    }
    __syncthreads();

    // ---- scores S[128x128]: 8x8 per thread ----
    const int tx = tid & 15;   // key cols  tx*8..+8
    const int ty = tid >> 4;   // query rows ty*8..+8
    unsigned long long acc[8][4];
#pragma unroll
    for (int i = 0; i < 8; ++i)
#pragma unroll
        for (int j = 0; j < 4; ++j) acc[i][j] = 0ull;

#pragma unroll 4
    for (int d = 0; d < 64; ++d) {
        const float* ap = &Qt[d * PQ + ty * 8];
        float4 a0 = *(const float4*)ap;
        float4 a1 = *(const float4*)(ap + 4);
        unsigned long long av[8];
        av[0] = dup2(a0.x); av[1] = dup2(a0.y);
        av[2] = dup2(a0.z); av[3] = dup2(a0.w);
        av[4] = dup2(a1.x); av[5] = dup2(a1.y);
        av[6] = dup2(a1.z); av[7] = dup2(a1.w);
        const unsigned long long* bp =
            (const unsigned long long*)&Kt[d * PQ + tx * 8];
        unsigned long long bv0 = bp[0], bv1 = bp[1], bv2 = bp[2], bv3 = bp[3];
#pragma unroll
        for (int i = 0; i < 8; ++i) {
            ffma2(acc[i][0], av[i], bv0);
            ffma2(acc[i][1], av[i], bv1);
            ffma2(acc[i][2], av[i], bv2);
            ffma2(acc[i][3], av[i], bv3);
        }
    }

    // ---- softmax over each row (16 lanes share a row; xor<=8 stays in group)
    float p[8][8];
#pragma unroll
    for (int i = 0; i < 8; ++i) {
        unpack2(acc[i][0], p[i][0], p[i][1]);
        unpack2(acc[i][1], p[i][2], p[i][3]);
        unpack2(acc[i][2], p[i][4], p[i][5]);
        unpack2(acc[i][3], p[i][6], p[i][7]);
    }
#pragma unroll
    for (int i = 0; i < 8; ++i) {
        float m = p[i][0];
#pragma unroll
        for (int j = 1; j < 8; ++j) m = fmaxf(m, p[i][j]);
#pragma unroll
        for (int off = 8; off >= 1; off >>= 1)
            m = fmaxf(m, __shfl_xor_sync(0xffffffffu, m, off));
        float ssum = 0.f;
#pragma unroll
        for (int j = 0; j < 8; ++j) {
            p[i][j] = __expf(p[i][j] - m);
            ssum += p[i][j];
        }
#pragma unroll
        for (int off = 8; off >= 1; off >>= 1)
            ssum += __shfl_xor_sync(0xffffffffu, ssum, off);
        const float inv = 1.0f / ssum;
#pragma unroll
        for (int j = 0; j < 8; ++j) p[i][j] *= inv;
    }

    __syncthreads();   // everyone done reading Qt/Kt before P overlays them
#pragma unroll
    for (int i = 0; i < 8; ++i) {
        float* pr = &Ps[(ty * 8 + i) * PQ + tx * 8];
#pragma unroll
        for (int jp = 0; jp < 4; ++jp)
            *(float2*)(pr + jp * 2) = make_float2(p[i][2 * jp], p[i][2 * jp + 1]);
    }
    __syncthreads();

    // ---- O[128x64] = P @ V : 4x8 per thread ----
    const int tx2 = tid & 7;    // cols tx2*8..+8
    const int ty2 = tid >> 3;   // rows ty2*4..+4
    unsigned long long oacc[4][4];
#pragma unroll
    for (int i = 0; i < 4; ++i)
#pragma unroll
        for (int j = 0; j < 4; ++j) oacc[i][j] = 0ull;

#pragma unroll 4
    for (int t = 0; t < 128; ++t) {
        unsigned long long av0 = dup2(Ps[(ty2 * 4 + 0) * PQ + t]);
        unsigned long long av1 = dup2(Ps[(ty2 * 4 + 1) * PQ + t]);
        unsigned long long av2 = dup2(Ps[(ty2 * 4 + 2) * PQ + t]);
        unsigned long long av3 = dup2(Ps[(ty2 * 4 + 3) * PQ + t]);
        const unsigned long long* vp =
            (const unsigned long long*)&Vs[t * 64 + tx2 * 8];
        unsigned long long bv0 = vp[0], bv1 = vp[1], bv2 = vp[2], bv3 = vp[3];
        ffma2(oacc[0][0], av0, bv0); ffma2(oacc[0][1], av0, bv1);
        ffma2(oacc[0][2], av0, bv2); ffma2(oacc[0][3], av0, bv3);
        ffma2(oacc[1][0], av1, bv0); ffma2(oacc[1][1], av1, bv1);
        ffma2(oacc[1][2], av1, bv2); ffma2(oacc[1][3], av1, bv3);
        ffma2(oacc[2][0], av2, bv0); ffma2(oacc[2][1], av2, bv1);
        ffma2(oacc[2][2], av2, bv2); ffma2(oacc[2][3], av2, bv3);
        ffma2(oacc[3][0], av3, bv0); ffma2(oacc[3][1], av3, bv1);
        ffma2(oacc[3][2], av3, bv2); ffma2(oacc[3][3], av3, bv3);
    }

    // ---- epilogue: out = relu(attn + R)   (R was placed in d_out by K1) ----
    float* op = out + ((size_t)b * Sn) * HDn + h * Dn;
#pragma unroll
    for (int i = 0; i < 4; ++i) {
        const int r = ty2 * 4 + i;
        float* rp = op + (size_t)r * HDn + tx2 * 8;
#pragma unroll
        for (int jp = 0; jp < 4; ++jp) {
            float o0, o1;
            unpack2(oacc[i][jp], o0, o1);
            float2 res = *(float2*)(rp + jp * 2);
            float v0 = res.x + o0;
            float v1 = res.y + o1;
            *(float2*)(rp + jp * 2) = make_float2(fmaxf(v0, 0.f), fmaxf(v1, 0.f));
        }
    }
}

// =============================================================================
extern "C" void kernel_launch(void* const* d_in, const int* in_sizes, int n_in,
                              void* d_out, int out_size)
{
    const float* X  = (const float*)d_in[0];
    const float* Wq = (const float*)d_in[1];
    const float* Wk = (const float*)d_in[2];
    const float* Wv = (const float*)d_in[3];
    const float* Wr = (const float*)d_in[4];
    float* out = (float*)d_out;

    const int smem_bytes = (2 * 64 * PQ + 128 * 64) * (int)sizeof(float); // 100352
    cudaFuncSetAttribute(attn_kernel,
                         cudaFuncAttributeMaxDynamicSharedMemorySize, smem_bytes);

    proj_kernel<<<dim3(16, 1024), 256>>>(X, Wq, Wk, Wv, Wr, out);
    attn_kernel<<<dim3(8, 1024), 256, smem_bytes>>>(out);
}

// round 5
// speedup vs baseline: 1.7035x; 1.7035x over previous
#include <cuda_runtime.h>
#include <cstdint>

// Problem constants
#define Bn  1024
#define Sn  128
#define En  256
#define Hn  8
#define Dn  64
#define HDn 512

// Scratch: Q,K,V per-(b,h) [128 x 64] row-major tiles (256 MiB each),
// plus transposed concatenated weights Wt[2048][256] (2 MiB).
__device__ float g_Q[67108864];
__device__ float g_K[67108864];
__device__ float g_V[67108864];
__device__ float g_Wt[2048 * 256];

// ---------------------------------------------------------------------------
// tf32 mma.sync helpers (arch-portable path: ptxas lowers to HMMA on sm_103a;
// tcgen05 is NOT usable here because the harness compiles PTX target sm_103)
// ---------------------------------------------------------------------------
__device__ __forceinline__ uint32_t f2tf32(float x) {
    uint32_t r;
    asm("cvt.rna.tf32.f32 %0, %1;" : "=r"(r) : "f"(x));
    return r;
}

__device__ __forceinline__ void mma_tf32(float* c,
                                         const uint32_t* a,
                                         const uint32_t* b) {
    asm volatile(
        "mma.sync.aligned.m16n8k8.row.col.f32.tf32.tf32.f32 "
        "{%0,%1,%2,%3}, {%4,%5,%6,%7}, {%8,%9}, {%0,%1,%2,%3};"
        : "+f"(c[0]), "+f"(c[1]), "+f"(c[2]), "+f"(c[3])
        : "r"(a[0]), "r"(a[1]), "r"(a[2]), "r"(a[3]),
          "r"(b[0]), "r"(b[1]));
}

// ---------------- f32x2 packed-FMA helpers (for the fp32 attn kernel) -------
__device__ __forceinline__ unsigned long long dup2(float a) {
    unsigned int u = __float_as_uint(a);
    unsigned long long r;
    asm("mov.b64 %0, {%1, %1};" : "=l"(r) : "r"(u));
    return r;
}
__device__ __forceinline__ void ffma2(unsigned long long &d,
                                      unsigned long long a,
                                      unsigned long long b) {
    asm("fma.rn.f32x2 %0, %1, %2, %0;" : "+l"(d) : "l"(a), "l"(b));
}
__device__ __forceinline__ void unpack2(unsigned long long v, float &lo, float &hi) {
    unsigned int a, b;
    asm("mov.b64 {%0, %1}, %2;" : "=r"(a), "=r"(b) : "l"(v));
    lo = __uint_as_float(a);
    hi = __uint_as_float(b);
}

// =============================================================================
// Kernel 0: weight transpose. Wt[w*512 + n][k] = W_w[k][n].
// grid (16, 8, 4), block (32, 8).
// =============================================================================
__global__ void wtrans_kernel(const float* __restrict__ Wq,
                              const float* __restrict__ Wk,
                              const float* __restrict__ Wv,
                              const float* __restrict__ Wr)
{
    __shared__ float t[32][33];
    const int wsel = blockIdx.z;
    const float* W = (wsel == 0) ? Wq : (wsel == 1) ? Wk : (wsel == 2) ? Wv : Wr;
    const int n0 = blockIdx.x * 32, k0 = blockIdx.y * 32;
    const int tx = threadIdx.x, ty = threadIdx.y;
#pragma unroll
    for (int i = 0; i < 32; i += 8)
        t[ty + i][tx] = W[(size_t)(k0 + ty + i) * HDn + n0 + tx];
    __syncthreads();
#pragma unroll
    for (int i = 0; i < 32; i += 8)
        g_Wt[(size_t)(wsel * HDn + n0 + ty + i) * En + k0 + tx] = t[tx][ty + i];
}

// =============================================================================
// Kernel 1: tf32 mma.sync projection GEMM.
// CTA (bx, b): C[128x128] = X_b[128x256] @ Wcat[:, bx*128 .. +128]
// 8 warps as 2(m) x 4(n); warp tile 64x32 = 4x4 m16n8k8 fragments.
// Smem: per-chunk [128 rows][32 k] tf32 (pitch 36), double buffered.
// =============================================================================
constexpr int PP = 36;   // smem pitch (floats): banks = 4*(lane/4)+lane%4, conflict-free

__global__ __launch_bounds__(256)
void proj_mma(const float* __restrict__ X, float* __restrict__ out)
{
    extern __shared__ uint32_t sm[];   // 2 bufs x (A 128*PP + B 128*PP)

    const int tid  = threadIdx.x;
    const int wid  = tid >> 5;
    const int lane = tid & 31;
    const int g    = lane >> 2;     // group id (row within fragment)
    const int tg   = lane & 3;      // thread-in-group (col within fragment)
    const int bx   = blockIdx.x;
    const int b    = blockIdx.y;
    const int w    = bx >> 2;
    const int ncol0 = (bx & 3) * 128;
    const int nbase = bx * 128;     // row base in g_Wt

    const int wm = wid >> 2;        // 0..1 -> m base wm*64
    const int wn = wid & 3;         // 0..3 -> n base wn*32

    const float4* A4 = (const float4*)(X + (size_t)b * Sn * En);
    const float4* W4 = (const float4*)g_Wt;

    // per-thread load coords: 4 float4 per matrix per chunk
    float4 pa[4], pb[4];
    int lrow[4], lkq[4];
#pragma unroll
    for (int i = 0; i < 4; ++i) {
        const int f4 = tid + i * 256;
        lrow[i] = f4 >> 3;
        lkq[i]  = f4 & 7;
    }

    auto ldg = [&](int c) {
#pragma unroll
        for (int i = 0; i < 4; ++i) {
            pa[i] = A4[lrow[i] * 64 + c * 8 + lkq[i]];
            pb[i] = W4[(size_t)(nbase + lrow[i]) * 64 + c * 8 + lkq[i]];
        }
    };
    auto sts = [&](int buf) {
        uint32_t* SA = sm + buf * (2 * 128 * PP);
        uint32_t* SB = SA + 128 * PP;
#pragma unroll
        for (int i = 0; i < 4; ++i) {
            const int off = lrow[i] * PP + lkq[i] * 4;
            uint4 va = make_uint4(f2tf32(pa[i].x), f2tf32(pa[i].y),
                                  f2tf32(pa[i].z), f2tf32(pa[i].w));
            uint4 vb = make_uint4(f2tf32(pb[i].x), f2tf32(pb[i].y),
                                  f2tf32(pb[i].z), f2tf32(pb[i].w));
            *(uint4*)(SA + off) = va;
            *(uint4*)(SB + off) = vb;
        }
    };

    float acc[4][4][4];
#pragma unroll
    for (int mt = 0; mt < 4; ++mt)
#pragma unroll
        for (int nt = 0; nt < 4; ++nt)
#pragma unroll
            for (int j = 0; j < 4; ++j) acc[mt][nt][j] = 0.f;

    ldg(0);
    sts(0);
    __syncthreads();

#pragma unroll 1
    for (int c = 0; c < 8; ++c) {
        const int buf = c & 1;
        if (c < 7) ldg(c + 1);

        const uint32_t* SA = sm + buf * (2 * 128 * PP);
        const uint32_t* SB = SA + 128 * PP;
#pragma unroll
        for (int ks = 0; ks < 4; ++ks) {
            const int k0 = ks * 8;
            uint32_t af[4][4], bf[4][2];
#pragma unroll
            for (int mt = 0; mt < 4; ++mt) {
                const int base = (wm * 64 + mt * 16 + g) * PP + k0 + tg;
                af[mt][0] = SA[base];
                af[mt][1] = SA[base + 8 * PP];
                af[mt][2] = SA[base + 4];
                af[mt][3] = SA[base + 8 * PP + 4];
            }
#pragma unroll
            for (int nt = 0; nt < 4; ++nt) {
                const int nb = (wn * 32 + nt * 8 + g) * PP + k0 + tg;
                bf[nt][0] = SB[nb];
                bf[nt][1] = SB[nb + 4];
            }
#pragma unroll
            for (int mt = 0; mt < 4; ++mt)
#pragma unroll
                for (int nt = 0; nt < 4; ++nt)
                    mma_tf32(acc[mt][nt], af[mt], bf[nt]);
        }

        if (c < 7) {
            __syncthreads();
            sts(buf ^ 1);
            __syncthreads();
        }
    }

    // Epilogue: fragment (mt,nt): rows wm*64+mt*16+g (+8), cols +tg*2 (+1)
#pragma unroll
    for (int mt = 0; mt < 4; ++mt) {
        const int row = wm * 64 + mt * 16 + g;
#pragma unroll
        for (int nt = 0; nt < 4; ++nt) {
            const int cl = wn * 32 + nt * 8 + tg * 2;   // col in CTA tile
            const int nw = ncol0 + cl;                  // col within weight
            float2 v01 = make_float2(acc[mt][nt][0], acc[mt][nt][1]);
            float2 v23 = make_float2(acc[mt][nt][2], acc[mt][nt][3]);
            if (w < 3) {
                float* G = (w == 0) ? g_Q : (w == 1) ? g_K : g_V;
                const int h  = nw >> 6;
                const int d0 = nw & 63;
                float* dst = G + (((size_t)(b * Hn + h) * Sn + row) * Dn + d0);
                *(float2*)dst            = v01;
                *(float2*)(dst + 8 * Dn) = v23;
            } else {
                float* dst = out + ((size_t)b * Sn + row) * HDn + nw;
                *(float2*)dst             = v01;
                *(float2*)(dst + 8 * HDn) = v23;
            }
        }
    }
}

// =============================================================================
// Kernel 2: per-(batch, head) attention: softmax(Q Kᵀ) V + residual, ReLU.
// (unchanged fp32/f32x2 version — mma.sync conversion is next round)
// =============================================================================
constexpr int PQ = 132;

__global__ __launch_bounds__(256)
void attn_kernel(float* __restrict__ out)
{
    extern __shared__ float smf[];
    float* Qt = smf;
    float* Kt = smf + 64 * PQ;
    float* Vs = smf + 2 * 64 * PQ;
    float* Ps = smf;

    const int tid = threadIdx.x;
    const int h = blockIdx.x, b = blockIdx.y;
    const size_t base = ((size_t)(b * Hn + h) * Sn) * Dn;
    const float4* Qg = (const float4*)(g_Q + base);
    const float4* Kg = (const float4*)(g_K + base);
    const float4* Vg = (const float4*)(g_V + base);

#pragma unroll
    for (int j = 0; j < 8; ++j) {
        const int f4 = tid + j * 256;
        const int s  = f4 >> 4;
        const int dq = (f4 & 15) * 4;
        float4 q = Qg[f4], kk = Kg[f4], v = Vg[f4];
        Qt[(dq + 0) * PQ + s] = q.x;  Qt[(dq + 1) * PQ + s] = q.y;
        Qt[(dq + 2) * PQ + s] = q.z;  Qt[(dq + 3) * PQ + s] = q.w;
        Kt[(dq + 0) * PQ + s] = kk.x; Kt[(dq + 1) * PQ + s] = kk.y;
        Kt[(dq + 2) * PQ + s] = kk.z; Kt[(dq + 3) * PQ + s] = kk.w;
        *(float4*)&Vs[f4 * 4] = v;
    }
    __syncthreads();

    const int tx = tid & 15;
    const int ty = tid >> 4;
    unsigned long long acc[8][4];
#pragma unroll
    for (int i = 0; i < 8; ++i)
#pragma unroll
        for (int j = 0; j < 4; ++j) acc[i][j] = 0ull;

#pragma unroll 4
    for (int d = 0; d < 64; ++d) {
        const float* ap = &Qt[d * PQ + ty * 8];
        float4 a0 = *(const float4*)ap;
        float4 a1 = *(const float4*)(ap + 4);
        unsigned long long av[8];
        av[0] = dup2(a0.x); av[1] = dup2(a0.y);
        av[2] = dup2(a0.z); av[3] = dup2(a0.w);
        av[4] = dup2(a1.x); av[5] = dup2(a1.y);
        av[6] = dup2(a1.z); av[7] = dup2(a1.w);
        const unsigned long long* bp =
            (const unsigned long long*)&Kt[d * PQ + tx * 8];
        unsigned long long bv0 = bp[0], bv1 = bp[1], bv2 = bp[2], bv3 = bp[3];
#pragma unroll
        for (int i = 0; i < 8; ++i) {
            ffma2(acc[i][0], av[i], bv0);
            ffma2(acc[i][1], av[i], bv1);
            ffma2(acc[i][2], av[i], bv2);
            ffma2(acc[i][3], av[i], bv3);
        }
    }

    float p[8][8];
#pragma unroll
    for (int i = 0; i < 8; ++i) {
        unpack2(acc[i][0], p[i][0], p[i][1]);
        unpack2(acc[i][1], p[i][2], p[i][3]);
        unpack2(acc[i][2], p[i][4], p[i][5]);
        unpack2(acc[i][3], p[i][6], p[i][7]);
    }
#pragma unroll
    for (int i = 0; i < 8; ++i) {
        float m = p[i][0];
#pragma unroll
        for (int j = 1; j < 8; ++j) m = fmaxf(m, p[i][j]);
#pragma unroll
        for (int off = 8; off >= 1; off >>= 1)
            m = fmaxf(m, __shfl_xor_sync(0xffffffffu, m, off));
        float ssum = 0.f;
#pragma unroll
        for (int j = 0; j < 8; ++j) {
            p[i][j] = __expf(p[i][j] - m);
            ssum += p[i][j];
        }
#pragma unroll
        for (int off = 8; off >= 1; off >>= 1)
            ssum += __shfl_xor_sync(0xffffffffu, ssum, off);
        const float inv = 1.0f / ssum;
#pragma unroll
        for (int j = 0; j < 8; ++j) p[i][j] *= inv;
    }

    __syncthreads();
#pragma unroll
    for (int i = 0; i < 8; ++i) {
        float* pr = &Ps[(ty * 8 + i) * PQ + tx * 8];
#pragma unroll
        for (int jp = 0; jp < 4; ++jp)
            *(float2*)(pr + jp * 2) = make_float2(p[i][2 * jp], p[i][2 * jp + 1]);
    }
    __syncthreads();

    const int tx2 = tid & 7;
    const int ty2 = tid >> 3;
    unsigned long long oacc[4][4];
#pragma unroll
    for (int i = 0; i < 4; ++i)
#pragma unroll
        for (int j = 0; j < 4; ++j) oacc[i][j] = 0ull;

#pragma unroll 4
    for (int t = 0; t < 128; ++t) {
        unsigned long long av0 = dup2(Ps[(ty2 * 4 + 0) * PQ + t]);
        unsigned long long av1 = dup2(Ps[(ty2 * 4 + 1) * PQ + t]);
        unsigned long long av2 = dup2(Ps[(ty2 * 4 + 2) * PQ + t]);
        unsigned long long av3 = dup2(Ps[(ty2 * 4 + 3) * PQ + t]);
        const unsigned long long* vp =
            (const unsigned long long*)&Vs[t * 64 + tx2 * 8];
        unsigned long long bv0 = vp[0], bv1 = vp[1], bv2 = vp[2], bv3 = vp[3];
        ffma2(oacc[0][0], av0, bv0); ffma2(oacc[0][1], av0, bv1);
        ffma2(oacc[0][2], av0, bv2); ffma2(oacc[0][3], av0, bv3);
        ffma2(oacc[1][0], av1, bv0); ffma2(oacc[1][1], av1, bv1);
        ffma2(oacc[1][2], av1, bv2); ffma2(oacc[1][3], av1, bv3);
        ffma2(oacc[2][0], av2, bv0); ffma2(oacc[2][1], av2, bv1);
        ffma2(oacc[2][2], av2, bv2); ffma2(oacc[2][3], av2, bv3);
        ffma2(oacc[3][0], av3, bv0); ffma2(oacc[3][1], av3, bv1);
        ffma2(oacc[3][2], av3, bv2); ffma2(oacc[3][3], av3, bv3);
    }

    float* op = out + ((size_t)b * Sn) * HDn + h * Dn;
#pragma unroll
    for (int i = 0; i < 4; ++i) {
        const int r = ty2 * 4 + i;
        float* rp = op + (size_t)r * HDn + tx2 * 8;
#pragma unroll
        for (int jp = 0; jp < 4; ++jp) {
            float o0, o1;
            unpack2(oacc[i][jp], o0, o1);
            float2 res = *(float2*)(rp + jp * 2);
            float v0 = res.x + o0;
            float v1 = res.y + o1;
            *(float2*)(rp + jp * 2) = make_float2(fmaxf(v0, 0.f), fmaxf(v1, 0.f));
        }
    }
}

// =============================================================================
extern "C" void kernel_launch(void* const* d_in, const int* in_sizes, int n_in,
                              void* d_out, int out_size)
{
    const float* X  = (const float*)d_in[0];
    const float* Wq = (const float*)d_in[1];
    const float* Wk = (const float*)d_in[2];
    const float* Wv = (const float*)d_in[3];
    const float* Wr = (const float*)d_in[4];
    float* out = (float*)d_out;

    const int attn_smem = (2 * 64 * PQ + 128 * 64) * (int)sizeof(float); // 100352
    const int proj_smem = 2 * 2 * 128 * PP * (int)sizeof(float);         // 73728
    cudaFuncSetAttribute(attn_kernel,
                         cudaFuncAttributeMaxDynamicSharedMemorySize, attn_smem);
    cudaFuncSetAttribute(proj_mma,
                         cudaFuncAttributeMaxDynamicSharedMemorySize, proj_smem);

    wtrans_kernel<<<dim3(16, 8, 4), dim3(32, 8)>>>(Wq, Wk, Wv, Wr);
    proj_mma<<<dim3(16, 1024), 256, proj_smem>>>(X, out);
    attn_kernel<<<dim3(8, 1024), 256, attn_smem>>>(out);
}

// round 6
// speedup vs baseline: 2.3946x; 1.4057x over previous
#include <cuda_runtime.h>
#include <cstdint>

// Problem constants
#define Bn  1024
#define Sn  128
#define En  256
#define Hn  8
#define Dn  64
#define HDn 512

// Scratch: Q,K,V per-(b,h) [128 x 64] row-major tiles (256 MiB each),
// plus transposed concatenated weights Wt[2048][256] (2 MiB).
__device__ float g_Q[67108864];
__device__ float g_K[67108864];
__device__ float g_V[67108864];
__device__ float g_Wt[2048 * 256];

// ---------------------------------------------------------------------------
// tf32 mma.sync helpers (arch-portable path: ptxas lowers to HMMA on sm_103a;
// tcgen05 is NOT usable here because the harness compiles PTX target sm_103)
// ---------------------------------------------------------------------------
__device__ __forceinline__ uint32_t f2tf32(float x) {
    uint32_t r;
    asm("cvt.rna.tf32.f32 %0, %1;" : "=r"(r) : "f"(x));
    return r;
}

__device__ __forceinline__ void mma_tf32(float* c,
                                         const uint32_t* a,
                                         const uint32_t* b) {
    asm volatile(
        "mma.sync.aligned.m16n8k8.row.col.f32.tf32.tf32.f32 "
        "{%0,%1,%2,%3}, {%4,%5,%6,%7}, {%8,%9}, {%0,%1,%2,%3};"
        : "+f"(c[0]), "+f"(c[1]), "+f"(c[2]), "+f"(c[3])
        : "r"(a[0]), "r"(a[1]), "r"(a[2]), "r"(a[3]),
          "r"(b[0]), "r"(b[1]));
}

// =============================================================================
// Kernel 0: weight transpose. Wt[w*512 + n][k] = W_w[k][n].
// =============================================================================
__global__ void wtrans_kernel(const float* __restrict__ Wq,
                              const float* __restrict__ Wk,
                              const float* __restrict__ Wv,
                              const float* __restrict__ Wr)
{
    __shared__ float t[32][33];
    const int wsel = blockIdx.z;
    const float* W = (wsel == 0) ? Wq : (wsel == 1) ? Wk : (wsel == 2) ? Wv : Wr;
    const int n0 = blockIdx.x * 32, k0 = blockIdx.y * 32;
    const int tx = threadIdx.x, ty = threadIdx.y;
#pragma unroll
    for (int i = 0; i < 32; i += 8)
        t[ty + i][tx] = W[(size_t)(k0 + ty + i) * HDn + n0 + tx];
    __syncthreads();
#pragma unroll
    for (int i = 0; i < 32; i += 8)
        g_Wt[(size_t)(wsel * HDn + n0 + ty + i) * En + k0 + tx] = t[tx][ty + i];
}

// =============================================================================
// Kernel 1: tf32 mma.sync projection GEMM (unchanged from Round 5, passing).
// =============================================================================
constexpr int PP = 36;

__global__ __launch_bounds__(256)
void proj_mma(const float* __restrict__ X, float* __restrict__ out)
{
    extern __shared__ uint32_t sm[];

    const int tid  = threadIdx.x;
    const int wid  = tid >> 5;
    const int lane = tid & 31;
    const int g    = lane >> 2;
    const int tg   = lane & 3;
    const int bx   = blockIdx.x;
    const int b    = blockIdx.y;
    const int w    = bx >> 2;
    const int ncol0 = (bx & 3) * 128;
    const int nbase = bx * 128;

    const int wm = wid >> 2;
    const int wn = wid & 3;

    const float4* A4 = (const float4*)(X + (size_t)b * Sn * En);
    const float4* W4 = (const float4*)g_Wt;

    float4 pa[4], pb[4];
    int lrow[4], lkq[4];
#pragma unroll
    for (int i = 0; i < 4; ++i) {
        const int f4 = tid + i * 256;
        lrow[i] = f4 >> 3;
        lkq[i]  = f4 & 7;
    }

    auto ldg = [&](int c) {
#pragma unroll
        for (int i = 0; i < 4; ++i) {
            pa[i] = A4[lrow[i] * 64 + c * 8 + lkq[i]];
            pb[i] = W4[(size_t)(nbase + lrow[i]) * 64 + c * 8 + lkq[i]];
        }
    };
    auto sts = [&](int buf) {
        uint32_t* SA = sm + buf * (2 * 128 * PP);
        uint32_t* SB = SA + 128 * PP;
#pragma unroll
        for (int i = 0; i < 4; ++i) {
            const int off = lrow[i] * PP + lkq[i] * 4;
            uint4 va = make_uint4(f2tf32(pa[i].x), f2tf32(pa[i].y),
                                  f2tf32(pa[i].z), f2tf32(pa[i].w));
            uint4 vb = make_uint4(f2tf32(pb[i].x), f2tf32(pb[i].y),
                                  f2tf32(pb[i].z), f2tf32(pb[i].w));
            *(uint4*)(SA + off) = va;
            *(uint4*)(SB + off) = vb;
        }
    };

    float acc[4][4][4];
#pragma unroll
    for (int mt = 0; mt < 4; ++mt)
#pragma unroll
        for (int nt = 0; nt < 4; ++nt)
#pragma unroll
            for (int j = 0; j < 4; ++j) acc[mt][nt][j] = 0.f;

    ldg(0);
    sts(0);
    __syncthreads();

#pragma unroll 1
    for (int c = 0; c < 8; ++c) {
        const int buf = c & 1;
        if (c < 7) ldg(c + 1);

        const uint32_t* SA = sm + buf * (2 * 128 * PP);
        const uint32_t* SB = SA + 128 * PP;
#pragma unroll
        for (int ks = 0; ks < 4; ++ks) {
            const int k0 = ks * 8;
            uint32_t af[4][4], bf[4][2];
#pragma unroll
            for (int mt = 0; mt < 4; ++mt) {
                const int base = (wm * 64 + mt * 16 + g) * PP + k0 + tg;
                af[mt][0] = SA[base];
                af[mt][1] = SA[base + 8 * PP];
                af[mt][2] = SA[base + 4];
                af[mt][3] = SA[base + 8 * PP + 4];
            }
#pragma unroll
            for (int nt = 0; nt < 4; ++nt) {
                const int nb = (wn * 32 + nt * 8 + g) * PP + k0 + tg;
                bf[nt][0] = SB[nb];
                bf[nt][1] = SB[nb + 4];
            }
#pragma unroll
            for (int mt = 0; mt < 4; ++mt)
#pragma unroll
                for (int nt = 0; nt < 4; ++nt)
                    mma_tf32(acc[mt][nt], af[mt], bf[nt]);
        }

        if (c < 7) {
            __syncthreads();
            sts(buf ^ 1);
            __syncthreads();
        }
    }

#pragma unroll
    for (int mt = 0; mt < 4; ++mt) {
        const int row = wm * 64 + mt * 16 + g;
#pragma unroll
        for (int nt = 0; nt < 4; ++nt) {
            const int cl = wn * 32 + nt * 8 + tg * 2;
            const int nw = ncol0 + cl;
            float2 v01 = make_float2(acc[mt][nt][0], acc[mt][nt][1]);
            float2 v23 = make_float2(acc[mt][nt][2], acc[mt][nt][3]);
            if (w < 3) {
                float* G = (w == 0) ? g_Q : (w == 1) ? g_K : g_V;
                const int h  = nw >> 6;
                const int d0 = nw & 63;
                float* dst = G + (((size_t)(b * Hn + h) * Sn + row) * Dn + d0);
                *(float2*)dst            = v01;
                *(float2*)(dst + 8 * Dn) = v23;
            } else {
                float* dst = out + ((size_t)b * Sn + row) * HDn + nw;
                *(float2*)dst             = v01;
                *(float2*)(dst + 8 * HDn) = v23;
            }
        }
    }
}

// =============================================================================
// Kernel 2: tf32 mma.sync attention. One CTA per (b,h), 256 threads, 8 warps.
// Warp w owns rows w*16..w*16+16 of the 128x128 score tile (all 128 cols).
//   QK^T : 8 k-steps x 16 n-frags -> acc[16][4]
//   softmax: each thread owns 2 full rows spread over its quad (shfl_xor 1,2)
//   P (unnormalized exp, tf32) -> smem, overlaying Q+K
//   PV   : 16 k-steps x 8 n-frags; epilogue applies 1/sum, +residual, ReLU
// Pitches: 68 (Q,K,V) and 132 (P): both ≡4 mod 32 -> all fragment LDS
// patterns map to banks 4g+tg / 4tg+g = conflict-free.
// =============================================================================
constexpr int PK  = 68;
constexpr int PPs = 132;

__global__ __launch_bounds__(256)
void attn_mma(float* __restrict__ out)
{
    extern __shared__ uint32_t smu[];
    uint32_t* SQ = smu;                    // [128][68] tf32
    uint32_t* SK = smu + 128 * PK;         // [128][68]
    uint32_t* SV = smu + 2 * 128 * PK;     // [128][68]
    uint32_t* SP = smu;                    // [128][132] overlays SQ+SK (67584<=69632)

    const int tid  = threadIdx.x;
    const int wid  = tid >> 5;
    const int lane = tid & 31;
    const int g    = lane >> 2;
    const int tg   = lane & 3;
    const int h = blockIdx.x, b = blockIdx.y;

    const size_t base = ((size_t)(b * Hn + h) * Sn) * Dn;
    const float4* Qg = (const float4*)(g_Q + base);
    const float4* Kg = (const float4*)(g_K + base);
    const float4* Vg = (const float4*)(g_V + base);

    // ---- stage Q,K,V as tf32, pitch 68 ----
#pragma unroll
    for (int i = 0; i < 8; ++i) {
        const int f4  = tid + i * 256;       // 0..2047
        const int row = f4 >> 4;
        const int c4  = (f4 & 15) * 4;
        float4 q = Qg[f4], k = Kg[f4], v = Vg[f4];
        *(uint4*)(SQ + row * PK + c4) =
            make_uint4(f2tf32(q.x), f2tf32(q.y), f2tf32(q.z), f2tf32(q.w));
        *(uint4*)(SK + row * PK + c4) =
            make_uint4(f2tf32(k.x), f2tf32(k.y), f2tf32(k.z), f2tf32(k.w));
        *(uint4*)(SV + row * PK + c4) =
            make_uint4(f2tf32(v.x), f2tf32(v.y), f2tf32(v.z), f2tf32(v.w));
    }
    __syncthreads();

    // ---- S = Q K^T ----
    float acc[16][4];
#pragma unroll
    for (int nt = 0; nt < 16; ++nt)
#pragma unroll
        for (int j = 0; j < 4; ++j) acc[nt][j] = 0.f;

    const uint32_t* Arow = SQ + (wid * 16 + g) * PK;
#pragma unroll
    for (int ks = 0; ks < 8; ++ks) {
        const int k0 = ks * 8;
        uint32_t af[4];
        af[0] = Arow[k0 + tg];
        af[1] = Arow[8 * PK + k0 + tg];
        af[2] = Arow[k0 + tg + 4];
        af[3] = Arow[8 * PK + k0 + tg + 4];
#pragma unroll
        for (int nt = 0; nt < 16; ++nt) {
            const uint32_t* Bp = SK + (nt * 8 + g) * PK + k0 + tg;
            uint32_t bf[2] = { Bp[0], Bp[4] };
            mma_tf32(acc[nt], af, bf);
        }
    }

    // ---- softmax over rows r0 = wid*16+g and r1 = r0+8 (quad-local) ----
    float m0 = -1e30f, m1 = -1e30f;
#pragma unroll
    for (int nt = 0; nt < 16; ++nt) {
        m0 = fmaxf(m0, fmaxf(acc[nt][0], acc[nt][1]));
        m1 = fmaxf(m1, fmaxf(acc[nt][2], acc[nt][3]));
    }
#pragma unroll
    for (int off = 2; off >= 1; off >>= 1) {
        m0 = fmaxf(m0, __shfl_xor_sync(0xffffffffu, m0, off));
        m1 = fmaxf(m1, __shfl_xor_sync(0xffffffffu, m1, off));
    }
    float s0 = 0.f, s1 = 0.f;
#pragma unroll
    for (int nt = 0; nt < 16; ++nt) {
        acc[nt][0] = __expf(acc[nt][0] - m0);
        acc[nt][1] = __expf(acc[nt][1] - m0);
        acc[nt][2] = __expf(acc[nt][2] - m1);
        acc[nt][3] = __expf(acc[nt][3] - m1);
        s0 += acc[nt][0] + acc[nt][1];
        s1 += acc[nt][2] + acc[nt][3];
    }
#pragma unroll
    for (int off = 2; off >= 1; off >>= 1) {
        s0 += __shfl_xor_sync(0xffffffffu, s0, off);
        s1 += __shfl_xor_sync(0xffffffffu, s1, off);
    }
    const float inv0 = 1.0f / s0;
    const float inv1 = 1.0f / s1;

    __syncthreads();   // all warps done reading SQ/SK before SP overlays them

    const int r0 = wid * 16 + g;
#pragma unroll
    for (int nt = 0; nt < 16; ++nt) {
        const int cl = nt * 8 + tg * 2;
        *(uint2*)(SP + r0 * PPs + cl) =
            make_uint2(f2tf32(acc[nt][0]), f2tf32(acc[nt][1]));
        *(uint2*)(SP + (r0 + 8) * PPs + cl) =
            make_uint2(f2tf32(acc[nt][2]), f2tf32(acc[nt][3]));
    }
    __syncthreads();

    // ---- O = P V ----
    float oacc[8][4];
#pragma unroll
    for (int nt = 0; nt < 8; ++nt)
#pragma unroll
        for (int j = 0; j < 4; ++j) oacc[nt][j] = 0.f;

    const uint32_t* Ap = SP + (wid * 16 + g) * PPs;
#pragma unroll
    for (int ks = 0; ks < 16; ++ks) {
        const int k0 = ks * 8;
        uint32_t af[4];
        af[0] = Ap[k0 + tg];
        af[1] = Ap[8 * PPs + k0 + tg];
        af[2] = Ap[k0 + tg + 4];
        af[3] = Ap[8 * PPs + k0 + tg + 4];
#pragma unroll
        for (int nt = 0; nt < 8; ++nt) {
            uint32_t bf[2];
            bf[0] = SV[(k0 + tg) * PK + nt * 8 + g];
            bf[1] = SV[(k0 + tg + 4) * PK + nt * 8 + g];
            mma_tf32(oacc[nt], af, bf);
        }
    }

    // ---- epilogue: normalize, +residual (already in out), ReLU ----
    float* op = out + ((size_t)b * Sn) * HDn + h * Dn;
#pragma unroll
    for (int nt = 0; nt < 8; ++nt) {
        const int d = nt * 8 + tg * 2;
        float* p0 = op + (size_t)r0 * HDn + d;
        float* p1 = op + (size_t)(r0 + 8) * HDn + d;
        float2 a0 = *(float2*)p0;
        float2 a1 = *(float2*)p1;
        float x0 = a0.x + oacc[nt][0] * inv0;
        float x1 = a0.y + oacc[nt][1] * inv0;
        float x2 = a1.x + oacc[nt][2] * inv1;
        float x3 = a1.y + oacc[nt][3] * inv1;
        *(float2*)p0 = make_float2(fmaxf(x0, 0.f), fmaxf(x1, 0.f));
        *(float2*)p1 = make_float2(fmaxf(x2, 0.f), fmaxf(x3, 0.f));
    }
}

// =============================================================================
extern "C" void kernel_launch(void* const* d_in, const int* in_sizes, int n_in,
                              void* d_out, int out_size)
{
    const float* X  = (const float*)d_in[0];
    const float* Wq = (const float*)d_in[1];
    const float* Wk = (const float*)d_in[2];
    const float* Wv = (const float*)d_in[3];
    const float* Wr = (const float*)d_in[4];
    float* out = (float*)d_out;

    const int proj_smem = 2 * 2 * 128 * PP * (int)sizeof(float);          // 73728
    const int attn_smem = (3 * 128 * PK) * (int)sizeof(uint32_t);         // 104448
    cudaFuncSetAttribute(proj_mma,
                         cudaFuncAttributeMaxDynamicSharedMemorySize, proj_smem);
    cudaFuncSetAttribute(attn_mma,
                         cudaFuncAttributeMaxDynamicSharedMemorySize, attn_smem);

    wtrans_kernel<<<dim3(16, 8, 4), dim3(32, 8)>>>(Wq, Wk, Wv, Wr);
    proj_mma<<<dim3(16, 1024), 256, proj_smem>>>(X, out);
    attn_mma<<<dim3(8, 1024), 256, attn_smem>>>(out);
}

// round 7
// speedup vs baseline: 3.0000x; 1.2528x over previous
#include <cuda_runtime.h>
#include <cstdint>

// Problem constants
#define Bn  1024
#define Sn  128
#define En  256
#define Hn  8
#define Dn  64
#define HDn 512

// Scratch (tf32 bit patterns stored in float arrays):
//   Q,K,V per-(b,h) [128 x 64] tiles, Xt = pre-converted inputs,
//   Wt = transposed + converted weights.
__device__ float g_Q[67108864];
__device__ float g_K[67108864];
__device__ float g_V[67108864];
__device__ float g_Xt[33554432];
__device__ float g_Wt[2048 * 256];

// ---------------------------------------------------------------------------
// Helpers. tcgen05 is unusable (harness PTX target is sm_103, no 'a'), so the
// tensor path is arch-portable mma.sync (HMMA).
// ---------------------------------------------------------------------------
__device__ __forceinline__ uint32_t smem_u32(const void* p) {
    uint32_t a;
    asm("{ .reg .u64 t; cvta.to.shared.u64 t, %1; cvt.u32.u64 %0, t; }"
        : "=r"(a) : "l"(p));
    return a;
}
__device__ __forceinline__ uint32_t f2tf32(float x) {
    uint32_t r;
    asm("cvt.rna.tf32.f32 %0, %1;" : "=r"(r) : "f"(x));
    return r;
}
__device__ __forceinline__ void mma_tf32(float* c,
                                         const uint32_t* a,
                                         const uint32_t* b) {
    asm volatile(
        "mma.sync.aligned.m16n8k8.row.col.f32.tf32.tf32.f32 "
        "{%0,%1,%2,%3}, {%4,%5,%6,%7}, {%8,%9}, {%0,%1,%2,%3};"
        : "+f"(c[0]), "+f"(c[1]), "+f"(c[2]), "+f"(c[3])
        : "r"(a[0]), "r"(a[1]), "r"(a[2]), "r"(a[3]),
          "r"(b[0]), "r"(b[1]));
}
__device__ __forceinline__ void cpa16(uint32_t saddr, const void* g) {
    asm volatile("cp.async.cg.shared.global [%0], [%1], 16;"
                 :: "r"(saddr), "l"(g) : "memory");
}
#define CP_COMMIT() asm volatile("cp.async.commit_group;" ::: "memory")
#define CP_WAIT(n)  asm volatile("cp.async.wait_group %0;" :: "n"(n) : "memory")

// =============================================================================
// Kernel 0a: convert X -> tf32 bits (RNA) in g_Xt.
// 32M floats; grid 8192 x 256, 4 float4 per thread.
// =============================================================================
__global__ void xconv_kernel(const float4* __restrict__ X)
{
    uint4* dst = (uint4*)g_Xt;
#pragma unroll
    for (int j = 0; j < 4; ++j) {
        const size_t i = (size_t)blockIdx.x * 1024 + j * 256 + threadIdx.x;
        float4 v = X[i];
        dst[i] = make_uint4(f2tf32(v.x), f2tf32(v.y), f2tf32(v.z), f2tf32(v.w));
    }
}

// =============================================================================
// Kernel 0b: weight transpose + tf32 convert. Wt[w*512 + n][k] = tf32(W_w[k][n])
// =============================================================================
__global__ void wtrans_kernel(const float* __restrict__ Wq,
                              const float* __restrict__ Wk,
                              const float* __restrict__ Wv,
                              const float* __restrict__ Wr)
{
    __shared__ float t[32][33];
    const int wsel = blockIdx.z;
    const float* W = (wsel == 0) ? Wq : (wsel == 1) ? Wk : (wsel == 2) ? Wv : Wr;
    const int n0 = blockIdx.x * 32, k0 = blockIdx.y * 32;
    const int tx = threadIdx.x, ty = threadIdx.y;
#pragma unroll
    for (int i = 0; i < 32; i += 8)
        t[ty + i][tx] = W[(size_t)(k0 + ty + i) * HDn + n0 + tx];
    __syncthreads();
    uint32_t* Wt = (uint32_t*)g_Wt;
#pragma unroll
    for (int i = 0; i < 32; i += 8)
        Wt[(size_t)(wsel * HDn + n0 + ty + i) * En + k0 + tx] = f2tf32(t[tx][ty + i]);
}

// =============================================================================
// Kernel 1: tf32 mma.sync projection GEMM with 3-stage cp.async pipeline.
// CTA (bx, b): C[128x128] = Xt_b[128x256] @ Wt[bx*128..+128, :]^T
// 8 warps 2(m) x 4(n), warp tile 64x32. One __syncthreads per K-chunk.
// =============================================================================
constexpr int PP = 36;                       // smem pitch (floats), conflict-free
constexpr int CHUNK_B = 128 * PP * 4;        // 18432 B per matrix per chunk
constexpr int SLOT_B  = 2 * CHUNK_B;         // A + B

__global__ __launch_bounds__(256)
void proj_mma(float* __restrict__ out)
{
    extern __shared__ uint32_t sm[];
    const uint32_t sb = smem_u32(sm);

    const int tid  = threadIdx.x;
    const int wid  = tid >> 5;
    const int lane = tid & 31;
    const int g    = lane >> 2;
    const int tg   = lane & 3;
    const int bx   = blockIdx.x;
    const int b    = blockIdx.y;
    const int w    = bx >> 2;
    const int ncol0 = (bx & 3) * 128;
    const int nbase = bx * 128;

    const int wm = wid >> 2;
    const int wn = wid & 3;

    const float4* A4 = (const float4*)(g_Xt + (size_t)b * Sn * En);
    const float4* W4 = (const float4*)g_Wt;

    int lrow[4], lkq[4];
    uint32_t soff[4];
#pragma unroll
    for (int i = 0; i < 4; ++i) {
        const int f4 = tid + i * 256;
        lrow[i] = f4 >> 3;
        lkq[i]  = f4 & 7;
        soff[i] = (uint32_t)(lrow[i] * PP + lkq[i] * 4) * 4;
    }

    auto issue = [&](int c) {
        const int slot = c % 3;
        const uint32_t a_s = sb + slot * SLOT_B;
        const uint32_t b_s = a_s + CHUNK_B;
#pragma unroll
        for (int i = 0; i < 4; ++i) {
            cpa16(a_s + soff[i], A4 + lrow[i] * 64 + c * 8 + lkq[i]);
            cpa16(b_s + soff[i], W4 + (size_t)(nbase + lrow[i]) * 64 + c * 8 + lkq[i]);
        }
        CP_COMMIT();
    };

    issue(0);
    issue(1);

    float acc[4][4][4];
#pragma unroll
    for (int mt = 0; mt < 4; ++mt)
#pragma unroll
        for (int nt = 0; nt < 4; ++nt)
#pragma unroll
            for (int j = 0; j < 4; ++j) acc[mt][nt][j] = 0.f;

#pragma unroll 1
    for (int c = 0; c < 8; ++c) {
        const int slot = c % 3;
        if (c < 7) { CP_WAIT(1); } else { CP_WAIT(0); }
        __syncthreads();           // chunk c visible; slot (c-1)%3 free for reuse
        if (c < 6) issue(c + 2);

        const uint32_t* SA = sm + slot * (SLOT_B / 4);
        const uint32_t* SB = SA + CHUNK_B / 4;
#pragma unroll
        for (int ks = 0; ks < 4; ++ks) {
            const int k0 = ks * 8;
            uint32_t af[4][4], bf[4][2];
#pragma unroll
            for (int mt = 0; mt < 4; ++mt) {
                const int base = (wm * 64 + mt * 16 + g) * PP + k0 + tg;
                af[mt][0] = SA[base];
                af[mt][1] = SA[base + 8 * PP];
                af[mt][2] = SA[base + 4];
                af[mt][3] = SA[base + 8 * PP + 4];
            }
#pragma unroll
            for (int nt = 0; nt < 4; ++nt) {
                const int nb = (wn * 32 + nt * 8 + g) * PP + k0 + tg;
                bf[nt][0] = SB[nb];
                bf[nt][1] = SB[nb + 4];
            }
#pragma unroll
            for (int mt = 0; mt < 4; ++mt)
#pragma unroll
                for (int nt = 0; nt < 4; ++nt)
                    mma_tf32(acc[mt][nt], af[mt], bf[nt]);
        }
    }

    // Epilogue: Q/K/V stored as tf32 bits (attn consumes them raw); R as fp32.
#pragma unroll
    for (int mt = 0; mt < 4; ++mt) {
        const int row = wm * 64 + mt * 16 + g;
#pragma unroll
        for (int nt = 0; nt < 4; ++nt) {
            const int cl = wn * 32 + nt * 8 + tg * 2;
            const int nw = ncol0 + cl;
            if (w < 3) {
                float* G = (w == 0) ? g_Q : (w == 1) ? g_K : g_V;
                const int h  = nw >> 6;
                const int d0 = nw & 63;
                uint32_t* dst = (uint32_t*)(G + (((size_t)(b * Hn + h) * Sn + row) * Dn + d0));
                *(uint2*)dst            = make_uint2(f2tf32(acc[mt][nt][0]), f2tf32(acc[mt][nt][1]));
                *(uint2*)(dst + 8 * Dn) = make_uint2(f2tf32(acc[mt][nt][2]), f2tf32(acc[mt][nt][3]));
            } else {
                float* dst = out + ((size_t)b * Sn + row) * HDn + nw;
                *(float2*)dst             = make_float2(acc[mt][nt][0], acc[mt][nt][1]);
                *(float2*)(dst + 8 * HDn) = make_float2(acc[mt][nt][2], acc[mt][nt][3]);
            }
        }
    }
}

// =============================================================================
// Kernel 2: tf32 mma.sync attention. One CTA per (b,h), 8 warps.
// Q,K,V arrive as tf32 bits -> staged raw via cp.async (no cvt).
// Pitches: SQ/SK 68, SV 72 (PV B-loads bank = 8*tg+g, conflict-free), SP 132.
// =============================================================================
constexpr int PK  = 68;
constexpr int PV  = 72;
constexpr int PPs = 132;

__global__ __launch_bounds__(256)
void attn_mma(float* __restrict__ out)
{
    extern __shared__ uint32_t smu[];
    uint32_t* SQ = smu;                         // [128][68]
    uint32_t* SK = smu + 128 * PK;              // [128][68]
    uint32_t* SV = smu + 2 * 128 * PK;          // [128][72]
    uint32_t* SP = smu;                         // [128][132] overlays SQ+SK

    const int tid  = threadIdx.x;
    const int wid  = tid >> 5;
    const int lane = tid & 31;
    const int g    = lane >> 2;
    const int tg   = lane & 3;
    const int h = blockIdx.x, b = blockIdx.y;

    const size_t base = ((size_t)(b * Hn + h) * Sn) * Dn;
    const float4* Qg = (const float4*)(g_Q + base);
    const float4* Kg = (const float4*)(g_K + base);
    const float4* Vg = (const float4*)(g_V + base);

    const uint32_t sb = smem_u32(smu);
    const uint32_t SKo = 128 * PK * 4;
    const uint32_t SVo = 2 * 128 * PK * 4;

    // ---- stage Q,K,V raw (already tf32 bits) via cp.async ----
#pragma unroll
    for (int i = 0; i < 8; ++i) {
        const int f4  = tid + i * 256;
        const int row = f4 >> 4;
        const int c4  = (f4 & 15) * 4;
        cpa16(sb + (uint32_t)(row * PK + c4) * 4,       Qg + f4);
        cpa16(sb + SKo + (uint32_t)(row * PK + c4) * 4, Kg + f4);
        cpa16(sb + SVo + (uint32_t)(row * PV + c4) * 4, Vg + f4);
    }
    CP_COMMIT();
    CP_WAIT(0);
    __syncthreads();

    // ---- S = Q K^T ----
    float acc[16][4];
#pragma unroll
    for (int nt = 0; nt < 16; ++nt)
#pragma unroll
        for (int j = 0; j < 4; ++j) acc[nt][j] = 0.f;

    const uint32_t* Arow = SQ + (wid * 16 + g) * PK;
#pragma unroll
    for (int ks = 0; ks < 8; ++ks) {
        const int k0 = ks * 8;
        uint32_t af[4];
        af[0] = Arow[k0 + tg];
        af[1] = Arow[8 * PK + k0 + tg];
        af[2] = Arow[k0 + tg + 4];
        af[3] = Arow[8 * PK + k0 + tg + 4];
#pragma unroll
        for (int nt = 0; nt < 16; ++nt) {
            const uint32_t* Bp = SK + (nt * 8 + g) * PK + k0 + tg;
            uint32_t bf[2] = { Bp[0], Bp[4] };
            mma_tf32(acc[nt], af, bf);
        }
    }

    // ---- softmax over rows r0 = wid*16+g and r1 = r0+8 (quad-local) ----
    float m0 = -1e30f, m1 = -1e30f;
#pragma unroll
    for (int nt = 0; nt < 16; ++nt) {
        m0 = fmaxf(m0, fmaxf(acc[nt][0], acc[nt][1]));
        m1 = fmaxf(m1, fmaxf(acc[nt][2], acc[nt][3]));
    }
#pragma unroll
    for (int off = 2; off >= 1; off >>= 1) {
        m0 = fmaxf(m0, __shfl_xor_sync(0xffffffffu, m0, off));
        m1 = fmaxf(m1, __shfl_xor_sync(0xffffffffu, m1, off));
    }
    float s0 = 0.f, s1 = 0.f;
#pragma unroll
    for (int nt = 0; nt < 16; ++nt) {
        acc[nt][0] = __expf(acc[nt][0] - m0);
        acc[nt][1] = __expf(acc[nt][1] - m0);
        acc[nt][2] = __expf(acc[nt][2] - m1);
        acc[nt][3] = __expf(acc[nt][3] - m1);
        s0 += acc[nt][0] + acc[nt][1];
        s1 += acc[nt][2] + acc[nt][3];
    }
#pragma unroll
    for (int off = 2; off >= 1; off >>= 1) {
        s0 += __shfl_xor_sync(0xffffffffu, s0, off);
        s1 += __shfl_xor_sync(0xffffffffu, s1, off);
    }
    const float inv0 = 1.0f / s0;
    const float inv1 = 1.0f / s1;

    __syncthreads();   // all warps done reading SQ/SK before SP overlays them

    const int r0 = wid * 16 + g;
#pragma unroll
    for (int nt = 0; nt < 16; ++nt) {
        const int cl = nt * 8 + tg * 2;
        *(uint2*)(SP + r0 * PPs + cl) =
            make_uint2(f2tf32(acc[nt][0]), f2tf32(acc[nt][1]));
        *(uint2*)(SP + (r0 + 8) * PPs + cl) =
            make_uint2(f2tf32(acc[nt][2]), f2tf32(acc[nt][3]));
    }
    __syncthreads();

    // ---- O = P V ----
    float oacc[8][4];
#pragma unroll
    for (int nt = 0; nt < 8; ++nt)
#pragma unroll
        for (int j = 0; j < 4; ++j) oacc[nt][j] = 0.f;

    const uint32_t* Ap = SP + (wid * 16 + g) * PPs;
#pragma unroll
    for (int ks = 0; ks < 16; ++ks) {
        const int k0 = ks * 8;
        uint32_t af[4];
        af[0] = Ap[k0 + tg];
        af[1] = Ap[8 * PPs + k0 + tg];
        af[2] = Ap[k0 + tg + 4];
        af[3] = Ap[8 * PPs + k0 + tg + 4];
#pragma unroll
        for (int nt = 0; nt < 8; ++nt) {
            uint32_t bf[2];
            bf[0] = SV[(k0 + tg) * PV + nt * 8 + g];
            bf[1] = SV[(k0 + tg + 4) * PV + nt * 8 + g];
            mma_tf32(oacc[nt], af, bf);
        }
    }

    // ---- epilogue: normalize, +residual (fp32 in out), ReLU ----
    float* op = out + ((size_t)b * Sn) * HDn + h * Dn;
#pragma unroll
    for (int nt = 0; nt < 8; ++nt) {
        const int d = nt * 8 + tg * 2;
        float* p0 = op + (size_t)r0 * HDn + d;
        float* p1 = op + (size_t)(r0 + 8) * HDn + d;
        float2 a0 = *(float2*)p0;
        float2 a1 = *(float2*)p1;
        float x0 = a0.x + oacc[nt][0] * inv0;
        float x1 = a0.y + oacc[nt][1] * inv0;
        float x2 = a1.x + oacc[nt][2] * inv1;
        float x3 = a1.y + oacc[nt][3] * inv1;
        *(float2*)p0 = make_float2(fmaxf(x0, 0.f), fmaxf(x1, 0.f));
        *(float2*)p1 = make_float2(fmaxf(x2, 0.f), fmaxf(x3, 0.f));
    }
}

// =============================================================================
extern "C" void kernel_launch(void* const* d_in, const int* in_sizes, int n_in,
                              void* d_out, int out_size)
{
    const float* X  = (const float*)d_in[0];
    const float* Wq = (const float*)d_in[1];
    const float* Wk = (const float*)d_in[2];
    const float* Wv = (const float*)d_in[3];
    const float* Wr = (const float*)d_in[4];
    float* out = (float*)d_out;

    const int proj_smem = 3 * SLOT_B;                                   // 110592
    const int attn_smem = (2 * 128 * PK + 128 * PV) * (int)sizeof(uint32_t); // 106496
    cudaFuncSetAttribute(proj_mma,
                         cudaFuncAttributeMaxDynamicSharedMemorySize, proj_smem);
    cudaFuncSetAttribute(attn_mma,
                         cudaFuncAttributeMaxDynamicSharedMemorySize, attn_smem);

    xconv_kernel<<<8192, 256>>>((const float4*)X);
    wtrans_kernel<<<dim3(16, 8, 4), dim3(32, 8)>>>(Wq, Wk, Wv, Wr);
    proj_mma<<<dim3(16, 1024), 256, proj_smem>>>(out);
    attn_mma<<<dim3(8, 1024), 256, attn_smem>>>(out);
}